// round 5
// baseline (speedup 1.0000x reference)
#include <cuda_runtime.h>
#include <math.h>

#define H 1024
#define W 1024
#define NB 32
#define NPIX (1024*1024)
#define SEGS 8
#define SEGH 128

// Scratch (allocation is forbidden; use device globals)
__device__ float g_x1[33554432];
__device__ float g_i2top[NB * 32 * 3 * W];   // seg-local i2 at rows 32k..32k+2
__device__ float g_colmax[NB * SEGS * W];
__device__ float g_carry [NB * SEGS * W];

// ---------------------------------------------------------------------------
// K1: fused convA(3x3)+BN+ReLU producing x1, plus segment-local bottom-up
// column cummax; emits i2 only at the 3 top rows of each 32-row band.
// ---------------------------------------------------------------------------
#define K1_COLS 128
#define K1_CH 16

__global__ __launch_bounds__(K1_COLS) void k1_convA_colscan(
    const float* __restrict__ x,
    const float* __restrict__ wa, const float* __restrict__ pba,
    const float* __restrict__ pga, const float* __restrict__ pbta,
    const float* __restrict__ pma, const float* __restrict__ pva)
{
    __shared__ float xs[K1_CH + 2][K1_COLS + 2];
    const int tid = threadIdx.x;
    const int c0  = blockIdx.x * K1_COLS;
    const int seg = blockIdx.y;
    const int b   = blockIdx.z;
    const int h0  = seg * SEGH;
    const size_t ib = (size_t)b * NPIX;

    float w[9];
#pragma unroll
    for (int i = 0; i < 9; i++) w[i] = __ldg(&wa[i]);
    const float sa = __ldg(pga) * rsqrtf(__ldg(pva) + 1e-5f);
    const float Ba = sa * (__ldg(pba) - __ldg(pma)) + __ldg(pbta);

    float m = 0.0f;
    const int col = c0 + tid;

    for (int k = 0; k < SEGH / K1_CH; k++) {
        const int hb = h0 + SEGH - K1_CH - k * K1_CH;
        __syncthreads();
        for (int idx = tid; idx < (K1_CH + 2) * (K1_COLS + 2); idx += K1_COLS) {
            int r  = idx / (K1_COLS + 2);
            int cc = idx - r * (K1_COLS + 2);
            int g  = hb - 1 + r;
            int c  = c0 - 1 + cc;
            float v = 0.0f;
            if ((unsigned)g < H && (unsigned)c < W)
                v = __ldg(&x[ib + (size_t)g * W + c]);
            xs[r][cc] = v;
        }
        __syncthreads();

        float rA[3], rB[3], rC[3];
#pragma unroll
        for (int kx = 0; kx < 3; kx++) {
            rA[kx] = xs[K1_CH - 1][tid + kx];
            rB[kx] = xs[K1_CH    ][tid + kx];
            rC[kx] = xs[K1_CH + 1][tid + kx];
        }
#pragma unroll
        for (int hh = K1_CH - 1; hh >= 0; hh--) {
            float acc = 0.0f;
#pragma unroll
            for (int kx = 0; kx < 3; kx++) {
                acc = fmaf(w[0 + kx], rA[kx], acc);
                acc = fmaf(w[3 + kx], rB[kx], acc);
                acc = fmaf(w[6 + kx], rC[kx], acc);
            }
            float v = fmaxf(fmaf(sa, acc, Ba), 0.0f);
            m = fmaxf(m, v);
            const int rg = hb + hh;
            g_x1[ib + (size_t)rg * W + col] = v;
            if ((rg & 31) < 3)
                g_i2top[(((size_t)b * 32 + (rg >> 5)) * 3 + (rg & 31)) * W + col] = m;
            if (hh > 0) {
#pragma unroll
                for (int kx = 0; kx < 3; kx++) {
                    rC[kx] = rB[kx];
                    rB[kx] = rA[kx];
                    rA[kx] = xs[hh - 1][tid + kx];
                }
            }
        }
    }
    g_colmax[((size_t)b * SEGS + seg) * W + col] = m;
}

__global__ __launch_bounds__(1024) void k1b_carry()
{
    const int b   = blockIdx.x;
    const int col = threadIdx.x;
    float c = 0.0f;
#pragma unroll
    for (int s = SEGS - 1; s >= 0; s--) {
        size_t o = ((size_t)b * SEGS + s) * W + col;
        g_carry[o] = c;
        c = fmaxf(c, g_colmax[o]);
    }
}

// ---------------------------------------------------------------------------
// K23: bottom-up pencil. 9 warps x (32 threads x 4 cols) = 128 cols/warp with
// a 4-col halo each side (120 unique cols/warp). All conv halos are intra-warp
// shfls; only the row-scan totals cross warps (1 barrier per row).
// ---------------------------------------------------------------------------
#define PROWS 32
#define WARPS 9
#define K23_THREADS (WARPS * 32)
#define UNIQ 120

__device__ __forceinline__ float4 contrib6(const float rw[6],
                                           float w0, float w1, float w2)
{
    float4 c;
    c.x = fmaf(w2, rw[2], fmaf(w1, rw[1], w0 * rw[0]));
    c.y = fmaf(w2, rw[3], fmaf(w1, rw[2], w0 * rw[1]));
    c.z = fmaf(w2, rw[4], fmaf(w1, rw[3], w0 * rw[2]));
    c.w = fmaf(w2, rw[5], fmaf(w1, rw[4], w0 * rw[3]));
    return c;
}

__device__ __forceinline__ float4 add4(float4 a, float4 b)
{
    return make_float4(a.x + b.x, a.y + b.y, a.z + b.z, a.w + b.w);
}

__device__ __forceinline__ void halo6(float4 v, float o[6])
{
    float L = __shfl_up_sync(0xffffffffu, v.w, 1);
    float R = __shfl_down_sync(0xffffffffu, v.x, 1);
    o[0] = L; o[1] = v.x; o[2] = v.y; o[3] = v.z; o[4] = v.w; o[5] = R;
}

__device__ __forceinline__ float4 ldrow4(const float* p, size_t ib, int r,
                                         int col0, bool colv)
{
    if (colv && (unsigned)r < H)
        return *(const float4*)(p + ib + (size_t)r * W + col0);
    return make_float4(0.f, 0.f, 0.f, 0.f);
}

__global__ __launch_bounds__(K23_THREADS) void k23_pencil(
    const float* __restrict__ x,
    const float* __restrict__ wb, const float* __restrict__ pbb,
    const float* __restrict__ pgb, const float* __restrict__ pbtb,
    const float* __restrict__ pmb, const float* __restrict__ pvb,
    const float* __restrict__ pwc, const float* __restrict__ pbc,
    const float* __restrict__ pgc, const float* __restrict__ pbtc,
    const float* __restrict__ pmc, const float* __restrict__ pvc,
    const float* __restrict__ wa, const float* __restrict__ pba,
    const float* __restrict__ pga, const float* __restrict__ pbta,
    const float* __restrict__ pma, const float* __restrict__ pva,
    const float* __restrict__ wd, const float* __restrict__ pbd,
    const float* __restrict__ pwe, const float* __restrict__ pbe,
    float* __restrict__ out)
{
    __shared__ float wtot[2][WARPS];

    const int tid  = threadIdx.x;
    const int lane = tid & 31;
    const int warp = tid >> 5;
    const int h0   = blockIdx.x * PROWS;
    const int b    = blockIdx.y;
    const size_t ib = (size_t)b * NPIX;
    const int col0 = warp * UNIQ - 4 + lane * 4;
    const bool colv   = ((unsigned)col0 < W);
    const bool storer = (lane >= 1) && (lane <= 30) && colv;

    const float sbn = __ldg(pgb) * rsqrtf(__ldg(pvb) + 1e-5f);
    const float Bb  = sbn * (__ldg(pbb) - __ldg(pmb)) + __ldg(pbtb);
    const float scn = __ldg(pgc) * rsqrtf(__ldg(pvc) + 1e-5f);
    const float c2x = __ldg(pwc) * scn;
    const float c2b = scn * (__ldg(pbc) - __ldg(pmc)) + __ldg(pbtc);
    const float san = __ldg(pga) * rsqrtf(__ldg(pva) + 1e-5f);
    const float Ba  = san * (__ldg(pba) - __ldg(pma)) + __ldg(pbta);
    const float bdv = __ldg(pbd);
    const float wev = __ldg(pwe);
    const float bev = __ldg(pbe);
    float wbv[9], wav[9], wdv[9];
#pragma unroll
    for (int i = 0; i < 9; i++) {
        wbv[i] = __ldg(&wb[i]);
        wav[i] = __ldg(&wa[i]);
        wdv[i] = __ldg(&wd[i]);
    }

    const float4 Z4 = make_float4(0.f, 0.f, 0.f, 0.f);
    float4 sAc = Z4, sBc = Z4, uAc = Z4, uBc = Z4, oAc = Z4, oBc = Z4;
    float4 m = Z4;

    float4 px1 = ldrow4(g_x1, ib, h0 + 34, col0, colv);
    float4 px  = ldrow4(x,   ib, h0 + 35, col0, colv);

    for (int it = 0; it < PROWS + 6; it++) {
        const int r = h0 + 34 - it;
        float4 cx1 = px1, cx = px;
        px1 = ldrow4(g_x1, ib, r - 1, col0, colv);
        px  = ldrow4(x,   ib, r,     col0, colv);

        // ---- i2 per column ----
        float4 i2;
        if (it < 3) {
            i2 = Z4;
            if (colv && (h0 + 32) < H) {
                const int band = (h0 + 32) >> 5;
                const int j    = 2 - it;
                float4 v  = *(const float4*)(g_i2top +
                              (((size_t)b * 32 + band) * 3 + j) * W + col0);
                float4 cr = *(const float4*)(g_carry +
                              ((size_t)b * SEGS + ((h0 + 32) >> 7)) * W + col0);
                i2.x = fmaxf(v.x, cr.x); i2.y = fmaxf(v.y, cr.y);
                i2.z = fmaxf(v.z, cr.z); i2.w = fmaxf(v.w, cr.w);
            }
            if (it == 2) m = i2;
        } else {
            m.x = fmaxf(m.x, cx1.x); m.y = fmaxf(m.y, cx1.y);
            m.z = fmaxf(m.z, cx1.z); m.w = fmaxf(m.w, cx1.w);
            i2 = m;
        }

        // ---- row suffix cummax (i1) ----
        float s3 = cx1.w;
        float s2 = fmaxf(cx1.z, s3);
        float s1 = fmaxf(cx1.y, s2);
        float s0 = fmaxf(cx1.x, s1);
        float incl = s0;
#pragma unroll
        for (int off = 1; off < 32; off <<= 1)
            incl = fmaxf(incl, __shfl_down_sync(0xffffffffu, incl, off));
        float restl = __shfl_down_sync(0xffffffffu, incl, 1);
        if (lane == 31) restl = 0.0f;
        float* wt = wtot[it & 1];
        if (lane == 2) wt[warp] = incl;   // max over cols >= 120*warp+4
        __syncthreads();
        float rest = restl;
        for (int w2 = warp + 1; w2 < WARPS; w2++) rest = fmaxf(rest, wt[w2]);

        float4 tv;
        tv.x = fmaxf(s0, rest) + i2.x;
        tv.y = fmaxf(s1, rest) + i2.y;
        tv.z = fmaxf(s2, rest) + i2.z;
        tv.w = fmaxf(s3, rest) + i2.w;
        if (r < 0) tv = Z4;               // top zero-pad (m may be nonzero)

        float t6[6];
        halo6(tv, t6);

        // ---- s stage: completes srow = r+1 ----
        float4 cf = contrib6(t6, wbv[0], wbv[1], wbv[2]);
        float4 cm = contrib6(t6, wbv[3], wbv[4], wbv[5]);
        float4 cn = contrib6(t6, wbv[6], wbv[7], wbv[8]);
        float4 sraw = add4(sAc, cf);
        sAc = add4(sBc, cm);
        sBc = cn;
        const int srow = r + 1;
        const bool sv = colv && ((unsigned)srow < H) && (srow <= h0 + 33);
        float4 sval;
        sval.x = sv ? fmaxf(fmaf(sbn, sraw.x, Bb) + fmaf(c2x, cx.x, c2b), 0.f) : 0.f;
        sval.y = sv ? fmaxf(fmaf(sbn, sraw.y, Bb) + fmaf(c2x, cx.y, c2b), 0.f) : 0.f;
        sval.z = sv ? fmaxf(fmaf(sbn, sraw.z, Bb) + fmaf(c2x, cx.z, c2b), 0.f) : 0.f;
        sval.w = sv ? fmaxf(fmaf(sbn, sraw.w, Bb) + fmaf(c2x, cx.w, c2b), 0.f) : 0.f;

        float s6[6];
        halo6(sval, s6);

        // ---- u stage: completes urow = r+2 ----
        cf = contrib6(s6, wav[0], wav[1], wav[2]);
        cm = contrib6(s6, wav[3], wav[4], wav[5]);
        cn = contrib6(s6, wav[6], wav[7], wav[8]);
        float4 uraw = add4(uAc, cf);
        uAc = add4(uBc, cm);
        uBc = cn;
        const int urow = r + 2;
        const bool uv = colv && ((unsigned)urow < H) && (urow <= h0 + 32);
        float4 uval;
        uval.x = uv ? fmaxf(fmaf(san, uraw.x, Ba), 0.f) : 0.f;
        uval.y = uv ? fmaxf(fmaf(san, uraw.y, Ba), 0.f) : 0.f;
        uval.z = uv ? fmaxf(fmaf(san, uraw.z, Ba), 0.f) : 0.f;
        uval.w = uv ? fmaxf(fmaf(san, uraw.w, Ba), 0.f) : 0.f;

        float u6[6];
        halo6(uval, u6);

        // ---- out stage: completes orow = r+3 ----
        cf = contrib6(u6, wdv[0], wdv[1], wdv[2]);
        cm = contrib6(u6, wdv[3], wdv[4], wdv[5]);
        cn = contrib6(u6, wdv[6], wdv[7], wdv[8]);
        float4 oraw = add4(oAc, cf);
        oAc = add4(oBc, cm);
        oBc = cn;
        const int orow = r + 3;
        if (storer && orow >= h0 && orow < h0 + PROWS) {
            float4 ov;
            ov.x = fmaf(wev, fmaxf(oraw.x + bdv, 0.f), bev);
            ov.y = fmaf(wev, fmaxf(oraw.y + bdv, 0.f), bev);
            ov.z = fmaf(wev, fmaxf(oraw.z + bdv, 0.f), bev);
            ov.w = fmaf(wev, fmaxf(oraw.w + bdv, 0.f), bev);
            *(float4*)(out + ib + (size_t)orow * W + col0) = ov;
        }
    }
}

// ---------------------------------------------------------------------------
extern "C" void kernel_launch(void* const* d_in, const int* in_sizes, int n_in,
                              void* d_out, int out_size)
{
    const float* x   = (const float*)d_in[0];
    const float* wa  = (const float*)d_in[1];
    const float* ba  = (const float*)d_in[2];
    const float* ga  = (const float*)d_in[3];
    const float* bta = (const float*)d_in[4];
    const float* ma  = (const float*)d_in[5];
    const float* va  = (const float*)d_in[6];
    const float* wb  = (const float*)d_in[7];
    const float* bb  = (const float*)d_in[8];
    const float* gb  = (const float*)d_in[9];
    const float* btb = (const float*)d_in[10];
    const float* mb  = (const float*)d_in[11];
    const float* vb  = (const float*)d_in[12];
    const float* wc  = (const float*)d_in[13];
    const float* bc  = (const float*)d_in[14];
    const float* gc  = (const float*)d_in[15];
    const float* btc = (const float*)d_in[16];
    const float* mc  = (const float*)d_in[17];
    const float* vc  = (const float*)d_in[18];
    const float* wd  = (const float*)d_in[19];
    const float* bd  = (const float*)d_in[20];
    const float* we  = (const float*)d_in[21];
    const float* be  = (const float*)d_in[22];
    float* out = (float*)d_out;

    dim3 g1(W / K1_COLS, SEGS, NB);
    k1_convA_colscan<<<g1, K1_COLS>>>(x, wa, ba, ga, bta, ma, va);

    k1b_carry<<<NB, 1024>>>();

    dim3 g23(H / PROWS, NB);
    k23_pencil<<<g23, K23_THREADS>>>(
        x,
        wb, bb, gb, btb, mb, vb,
        wc, bc, gc, btc, mc, vc,
        wa, ba, ga, bta, ma, va,
        wd, bd, we, be,
        out);
}

// round 6
// speedup vs baseline: 1.5345x; 1.5345x over previous
#include <cuda_runtime.h>
#include <math.h>

#define H 1024
#define W 1024
#define NB 32
#define NPIX (1024*1024)
#define SEGS 8
#define SEGH 128

// Scratch (allocation is forbidden; use device globals)
__device__ float g_x1[33554432];
__device__ float g_i2top[NB * 32 * 3 * W];   // seg-local i2 at rows 32k..32k+2
__device__ float g_colmax[NB * SEGS * W];
__device__ float g_carry [NB * SEGS * W];

// ---------------------------------------------------------------------------
// K1: fused convA(3x3)+BN+ReLU producing x1, plus segment-local bottom-up
// column cummax; emits i2 only at the 3 lowest-index rows of each 32-row band.
// ---------------------------------------------------------------------------
#define K1_COLS 128
#define K1_CH 16

__global__ __launch_bounds__(K1_COLS) void k1_convA_colscan(
    const float* __restrict__ x,
    const float* __restrict__ wa, const float* __restrict__ pba,
    const float* __restrict__ pga, const float* __restrict__ pbta,
    const float* __restrict__ pma, const float* __restrict__ pva)
{
    __shared__ float xs[K1_CH + 2][K1_COLS + 2];
    const int tid = threadIdx.x;
    const int c0  = blockIdx.x * K1_COLS;
    const int seg = blockIdx.y;
    const int b   = blockIdx.z;
    const int h0  = seg * SEGH;
    const size_t ib = (size_t)b * NPIX;

    float w[9];
#pragma unroll
    for (int i = 0; i < 9; i++) w[i] = __ldg(&wa[i]);
    const float sa = __ldg(pga) * rsqrtf(__ldg(pva) + 1e-5f);
    const float Ba = sa * (__ldg(pba) - __ldg(pma)) + __ldg(pbta);

    float m = 0.0f;
    const int col = c0 + tid;

    for (int k = 0; k < SEGH / K1_CH; k++) {
        const int hb = h0 + SEGH - K1_CH - k * K1_CH;
        __syncthreads();
        // main columns: coalesced, no div/mod
#pragma unroll
        for (int r = 0; r < K1_CH + 2; r++) {
            int g = hb - 1 + r;
            float v = 0.0f;
            if ((unsigned)g < H) v = __ldg(&x[ib + (size_t)g * W + col]);
            xs[r][tid + 1] = v;
        }
        // halo columns
        if (tid < K1_CH + 2) {
            int g = hb - 1 + tid, c = c0 - 1;
            float v = 0.0f;
            if ((unsigned)g < H && c >= 0) v = __ldg(&x[ib + (size_t)g * W + c]);
            xs[tid][0] = v;
        } else if (tid >= 32 && tid < 32 + K1_CH + 2) {
            int g = hb - 1 + (tid - 32), c = c0 + K1_COLS;
            float v = 0.0f;
            if ((unsigned)g < H && c < W) v = __ldg(&x[ib + (size_t)g * W + c]);
            xs[tid - 32][K1_COLS + 1] = v;
        }
        __syncthreads();

        float rA[3], rB[3], rC[3];
#pragma unroll
        for (int kx = 0; kx < 3; kx++) {
            rA[kx] = xs[K1_CH - 1][tid + kx];
            rB[kx] = xs[K1_CH    ][tid + kx];
            rC[kx] = xs[K1_CH + 1][tid + kx];
        }
#pragma unroll
        for (int hh = K1_CH - 1; hh >= 0; hh--) {
            float acc = 0.0f;
#pragma unroll
            for (int kx = 0; kx < 3; kx++) {
                acc = fmaf(w[0 + kx], rA[kx], acc);
                acc = fmaf(w[3 + kx], rB[kx], acc);
                acc = fmaf(w[6 + kx], rC[kx], acc);
            }
            float v = fmaxf(fmaf(sa, acc, Ba), 0.0f);
            m = fmaxf(m, v);
            const int rg = hb + hh;
            g_x1[ib + (size_t)rg * W + col] = v;
            if ((rg & 31) < 3)
                g_i2top[(((size_t)b * 32 + (rg >> 5)) * 3 + (rg & 31)) * W + col] = m;
            if (hh > 0) {
#pragma unroll
                for (int kx = 0; kx < 3; kx++) {
                    rC[kx] = rB[kx];
                    rB[kx] = rA[kx];
                    rA[kx] = xs[hh - 1][tid + kx];
                }
            }
        }
    }
    g_colmax[((size_t)b * SEGS + seg) * W + col] = m;
}

__global__ __launch_bounds__(1024) void k1b_carry()
{
    const int b   = blockIdx.x;
    const int col = threadIdx.x;
    float c = 0.0f;
#pragma unroll
    for (int s = SEGS - 1; s >= 0; s--) {
        size_t o = ((size_t)b * SEGS + s) * W + col;
        g_carry[o] = c;
        c = fmaxf(c, g_colmax[o]);
    }
}

// ---------------------------------------------------------------------------
// K23: bottom-up pencil, full-width (256 threads x 4 cols = 1024), TWO rows
// per iteration: interleaved row scans, 4 barriers per 2 rows.
// i2 kept in registers (warm-up from g_i2top + g_carry).
// ---------------------------------------------------------------------------
#define PROWS 32
#define WARPS 8

__device__ __forceinline__ float4 contrib6(const float rw[6],
                                           float w0, float w1, float w2)
{
    float4 c;
    c.x = fmaf(w2, rw[2], fmaf(w1, rw[1], w0 * rw[0]));
    c.y = fmaf(w2, rw[3], fmaf(w1, rw[2], w0 * rw[1]));
    c.z = fmaf(w2, rw[4], fmaf(w1, rw[3], w0 * rw[2]));
    c.w = fmaf(w2, rw[5], fmaf(w1, rw[4], w0 * rw[3]));
    return c;
}

__device__ __forceinline__ float4 add4(float4 a, float4 b)
{
    return make_float4(a.x + b.x, a.y + b.y, a.z + b.z, a.w + b.w);
}

// Bottom-up stage application: returns completed raw row, shifts accumulators.
__device__ __forceinline__ float4 stage_apply(const float r6[6],
                                              const float wv[9],
                                              float4& Ac, float4& Bc)
{
    float4 cf = contrib6(r6, wv[0], wv[1], wv[2]);   // completes row below
    float4 cm = contrib6(r6, wv[3], wv[4], wv[5]);
    float4 cn = contrib6(r6, wv[6], wv[7], wv[8]);
    float4 raw = add4(Ac, cf);
    Ac = add4(Bc, cm);
    Bc = cn;
    return raw;
}

// Two-row halo exchange; ONE barrier. eL/eR are 16-float arrays ([2][8]).
__device__ __forceinline__ void exchange2(
    float4 vA, float4 vB, float oA[6], float oB[6],
    float* eL, float* eR, int lane, int warp)
{
    float LA = __shfl_up_sync(0xffffffffu, vA.w, 1);
    float RA = __shfl_down_sync(0xffffffffu, vA.x, 1);
    float LB = __shfl_up_sync(0xffffffffu, vB.w, 1);
    float RB = __shfl_down_sync(0xffffffffu, vB.x, 1);
    if (lane == 31) { eL[warp] = vA.w; eL[8 + warp] = vB.w; }
    if (lane == 0)  { eR[warp] = vA.x; eR[8 + warp] = vB.x; }
    __syncthreads();
    if (lane == 0) {
        LA = warp > 0 ? eL[warp - 1] : 0.0f;
        LB = warp > 0 ? eL[8 + warp - 1] : 0.0f;
    }
    if (lane == 31) {
        RA = warp < 7 ? eR[warp + 1] : 0.0f;
        RB = warp < 7 ? eR[8 + warp + 1] : 0.0f;
    }
    oA[0] = LA; oA[1] = vA.x; oA[2] = vA.y; oA[3] = vA.z; oA[4] = vA.w; oA[5] = RA;
    oB[0] = LB; oB[1] = vB.x; oB[2] = vB.y; oB[3] = vB.z; oB[4] = vB.w; oB[5] = RB;
}

__device__ __forceinline__ float4 ldrow4(const float* p, size_t ib, int r, int col0)
{
    if ((unsigned)r < H)
        return *(const float4*)(p + ib + (size_t)r * W + col0);
    return make_float4(0.f, 0.f, 0.f, 0.f);
}

__global__ __launch_bounds__(256) void k23_pencil(
    const float* __restrict__ x,
    const float* __restrict__ wb, const float* __restrict__ pbb,
    const float* __restrict__ pgb, const float* __restrict__ pbtb,
    const float* __restrict__ pmb, const float* __restrict__ pvb,
    const float* __restrict__ pwc, const float* __restrict__ pbc,
    const float* __restrict__ pgc, const float* __restrict__ pbtc,
    const float* __restrict__ pmc, const float* __restrict__ pvc,
    const float* __restrict__ wa, const float* __restrict__ pba,
    const float* __restrict__ pga, const float* __restrict__ pbta,
    const float* __restrict__ pma, const float* __restrict__ pva,
    const float* __restrict__ wd, const float* __restrict__ pbd,
    const float* __restrict__ pwe, const float* __restrict__ pbe,
    float* __restrict__ out)
{
    __shared__ float wtA[WARPS], wtB[WARPS];
    __shared__ float eTL[16], eTR[16], eSL[16], eSR[16], eUL[16], eUR[16];

    const int tid  = threadIdx.x;
    const int lane = tid & 31;
    const int warp = tid >> 5;
    const int h0   = blockIdx.x * PROWS;
    const int b    = blockIdx.y;
    const size_t ib = (size_t)b * NPIX;
    const int col0 = tid * 4;

    const float sbn = __ldg(pgb) * rsqrtf(__ldg(pvb) + 1e-5f);
    const float Bb  = sbn * (__ldg(pbb) - __ldg(pmb)) + __ldg(pbtb);
    const float scn = __ldg(pgc) * rsqrtf(__ldg(pvc) + 1e-5f);
    const float c2x = __ldg(pwc) * scn;
    const float c2b = scn * (__ldg(pbc) - __ldg(pmc)) + __ldg(pbtc);
    const float san = __ldg(pga) * rsqrtf(__ldg(pva) + 1e-5f);
    const float Ba  = san * (__ldg(pba) - __ldg(pma)) + __ldg(pbta);
    const float bdv = __ldg(pbd);
    const float wev = __ldg(pwe);
    const float bev = __ldg(pbe);
    float wbv[9], wav[9], wdv[9];
#pragma unroll
    for (int i = 0; i < 9; i++) {
        wbv[i] = __ldg(&wb[i]);
        wav[i] = __ldg(&wa[i]);
        wdv[i] = __ldg(&wd[i]);
    }

    const float4 Z4 = make_float4(0.f, 0.f, 0.f, 0.f);
    float4 sAc = Z4, sBc = Z4, uAc = Z4, uBc = Z4, oAc = Z4, oBc = Z4;
    float4 m = Z4;

    // warm-up data (rows h0+32..h0+34), valid only if h0+32 < H
    const bool warm = (h0 + 32) < H;
    float4 cwv = Z4;
    if (warm)
        cwv = *(const float4*)(g_carry + ((size_t)b * SEGS + ((h0 + 32) >> 7)) * W + col0);
    const int band = (h0 + 32) >> 5;

    // prefetch first pair: rows rH=h0+34, rL=h0+33; x rows rH+1, rH
    float4 p_x1H = ldrow4(g_x1, ib, h0 + 34, col0);
    float4 p_x1L = ldrow4(g_x1, ib, h0 + 33, col0);
    float4 p_xH  = ldrow4(x,    ib, h0 + 35, col0);
    float4 p_xL  = ldrow4(x,    ib, h0 + 34, col0);

    for (int it = 0; it < (PROWS + 6) / 2; it++) {
        const int rH = h0 + 34 - 2 * it;
        const int rL = rH - 1;
        float4 cx1H = p_x1H, cx1L = p_x1L, cxH = p_xH, cxL = p_xL;
        // prefetch next pair
        p_x1H = ldrow4(g_x1, ib, rH - 2, col0);
        p_x1L = ldrow4(g_x1, ib, rH - 3, col0);
        p_xH  = ldrow4(x,    ib, rH - 1, col0);
        p_xL  = ldrow4(x,    ib, rH - 2, col0);

        // ---- i2 per column (register, warm-up from i2top+carry) ----
        float4 i2H, i2L;
        if (it == 0) {
            i2H = Z4; i2L = Z4;
            if (warm) {
                float4 v2 = *(const float4*)(g_i2top + (((size_t)b * 32 + band) * 3 + 2) * W + col0);
                float4 v1 = *(const float4*)(g_i2top + (((size_t)b * 32 + band) * 3 + 1) * W + col0);
                i2H.x = fmaxf(v2.x, cwv.x); i2H.y = fmaxf(v2.y, cwv.y);
                i2H.z = fmaxf(v2.z, cwv.z); i2H.w = fmaxf(v2.w, cwv.w);
                i2L.x = fmaxf(v1.x, cwv.x); i2L.y = fmaxf(v1.y, cwv.y);
                i2L.z = fmaxf(v1.z, cwv.z); i2L.w = fmaxf(v1.w, cwv.w);
            }
        } else if (it == 1) {
            i2H = Z4;
            if (warm) {
                float4 v0 = *(const float4*)(g_i2top + (((size_t)b * 32 + band) * 3 + 0) * W + col0);
                i2H.x = fmaxf(v0.x, cwv.x); i2H.y = fmaxf(v0.y, cwv.y);
                i2H.z = fmaxf(v0.z, cwv.z); i2H.w = fmaxf(v0.w, cwv.w);
            }
            m = i2H;
            m.x = fmaxf(m.x, cx1L.x); m.y = fmaxf(m.y, cx1L.y);
            m.z = fmaxf(m.z, cx1L.z); m.w = fmaxf(m.w, cx1L.w);
            i2L = m;
        } else {
            m.x = fmaxf(m.x, cx1H.x); m.y = fmaxf(m.y, cx1H.y);
            m.z = fmaxf(m.z, cx1H.z); m.w = fmaxf(m.w, cx1H.w);
            i2H = m;
            m.x = fmaxf(m.x, cx1L.x); m.y = fmaxf(m.y, cx1L.y);
            m.z = fmaxf(m.z, cx1L.z); m.w = fmaxf(m.w, cx1L.w);
            i2L = m;
        }

        // ---- interleaved row suffix cummax for both rows ----
        float h3 = cx1H.w;
        float h2 = fmaxf(cx1H.z, h3);
        float h1 = fmaxf(cx1H.y, h2);
        float h0s = fmaxf(cx1H.x, h1);
        float l3 = cx1L.w;
        float l2 = fmaxf(cx1L.z, l3);
        float l1 = fmaxf(cx1L.y, l2);
        float l0s = fmaxf(cx1L.x, l1);
        float inH = h0s, inL = l0s;
#pragma unroll
        for (int off = 1; off < 32; off <<= 1) {
            inH = fmaxf(inH, __shfl_down_sync(0xffffffffu, inH, off));
            inL = fmaxf(inL, __shfl_down_sync(0xffffffffu, inL, off));
        }
        float rsH = __shfl_down_sync(0xffffffffu, inH, 1);
        float rsL = __shfl_down_sync(0xffffffffu, inL, 1);
        if (lane == 31) { rsH = 0.0f; rsL = 0.0f; }
        if (lane == 0)  { wtA[warp] = inH; wtB[warp] = inL; }
        __syncthreads();                                        // bar 1
#pragma unroll
        for (int w2 = 0; w2 < WARPS; w2++)
            if (w2 > warp) { rsH = fmaxf(rsH, wtA[w2]); rsL = fmaxf(rsL, wtB[w2]); }

        float4 tvH, tvL;
        tvH.x = fmaxf(h0s, rsH) + i2H.x; tvH.y = fmaxf(h1, rsH) + i2H.y;
        tvH.z = fmaxf(h2, rsH) + i2H.z;  tvH.w = fmaxf(h3, rsH) + i2H.w;
        tvL.x = fmaxf(l0s, rsL) + i2L.x; tvL.y = fmaxf(l1, rsL) + i2L.y;
        tvL.z = fmaxf(l2, rsL) + i2L.z;  tvL.w = fmaxf(l3, rsL) + i2L.w;
        if (rH < 0) tvH = Z4;
        if (rL < 0) tvL = Z4;

        float t6H[6], t6L[6];
        exchange2(tvH, tvL, t6H, t6L, eTL, eTR, lane, warp);    // bar 2

        // ---- s stage: completes rows rH+1 (from tH) then rH (from tL) ----
        float4 srawH = stage_apply(t6H, wbv, sAc, sBc);
        float4 srawL = stage_apply(t6L, wbv, sAc, sBc);
        const int sH = rH + 1, sL = rH;
        const bool svH = ((unsigned)sH < H) && (sH >= h0 - 2) && (sH <= h0 + 33);
        const bool svL = ((unsigned)sL < H) && (sL >= h0 - 2) && (sL <= h0 + 33);
        float4 svalH, svalL;
        svalH.x = svH ? fmaxf(fmaf(sbn, srawH.x, Bb) + fmaf(c2x, cxH.x, c2b), 0.f) : 0.f;
        svalH.y = svH ? fmaxf(fmaf(sbn, srawH.y, Bb) + fmaf(c2x, cxH.y, c2b), 0.f) : 0.f;
        svalH.z = svH ? fmaxf(fmaf(sbn, srawH.z, Bb) + fmaf(c2x, cxH.z, c2b), 0.f) : 0.f;
        svalH.w = svH ? fmaxf(fmaf(sbn, srawH.w, Bb) + fmaf(c2x, cxH.w, c2b), 0.f) : 0.f;
        svalL.x = svL ? fmaxf(fmaf(sbn, srawL.x, Bb) + fmaf(c2x, cxL.x, c2b), 0.f) : 0.f;
        svalL.y = svL ? fmaxf(fmaf(sbn, srawL.y, Bb) + fmaf(c2x, cxL.y, c2b), 0.f) : 0.f;
        svalL.z = svL ? fmaxf(fmaf(sbn, srawL.z, Bb) + fmaf(c2x, cxL.z, c2b), 0.f) : 0.f;
        svalL.w = svL ? fmaxf(fmaf(sbn, srawL.w, Bb) + fmaf(c2x, cxL.w, c2b), 0.f) : 0.f;

        float s6H[6], s6L[6];
        exchange2(svalH, svalL, s6H, s6L, eSL, eSR, lane, warp); // bar 3

        // ---- u stage: completes rows rH+2, rH+1 ----
        float4 urawH = stage_apply(s6H, wav, uAc, uBc);
        float4 urawL = stage_apply(s6L, wav, uAc, uBc);
        const int uH = rH + 2, uL = rH + 1;
        const bool uvH = ((unsigned)uH < H) && (uH >= h0 - 1) && (uH <= h0 + 32);
        const bool uvL = ((unsigned)uL < H) && (uL >= h0 - 1) && (uL <= h0 + 32);
        float4 uvalH, uvalL;
        uvalH.x = uvH ? fmaxf(fmaf(san, urawH.x, Ba), 0.f) : 0.f;
        uvalH.y = uvH ? fmaxf(fmaf(san, urawH.y, Ba), 0.f) : 0.f;
        uvalH.z = uvH ? fmaxf(fmaf(san, urawH.z, Ba), 0.f) : 0.f;
        uvalH.w = uvH ? fmaxf(fmaf(san, urawH.w, Ba), 0.f) : 0.f;
        uvalL.x = uvL ? fmaxf(fmaf(san, urawL.x, Ba), 0.f) : 0.f;
        uvalL.y = uvL ? fmaxf(fmaf(san, urawL.y, Ba), 0.f) : 0.f;
        uvalL.z = uvL ? fmaxf(fmaf(san, urawL.z, Ba), 0.f) : 0.f;
        uvalL.w = uvL ? fmaxf(fmaf(san, urawL.w, Ba), 0.f) : 0.f;

        float u6H[6], u6L[6];
        exchange2(uvalH, uvalL, u6H, u6L, eUL, eUR, lane, warp); // bar 4

        // ---- out stage: completes rows rH+3, rH+2 ----
        float4 orawH = stage_apply(u6H, wdv, oAc, oBc);
        float4 orawL = stage_apply(u6L, wdv, oAc, oBc);
        const int oH = rH + 3, oL = rH + 2;
        if (oH >= h0 && oH < h0 + PROWS) {
            float4 ov;
            ov.x = fmaf(wev, fmaxf(orawH.x + bdv, 0.f), bev);
            ov.y = fmaf(wev, fmaxf(orawH.y + bdv, 0.f), bev);
            ov.z = fmaf(wev, fmaxf(orawH.z + bdv, 0.f), bev);
            ov.w = fmaf(wev, fmaxf(orawH.w + bdv, 0.f), bev);
            *(float4*)(out + ib + (size_t)oH * W + col0) = ov;
        }
        if (oL >= h0 && oL < h0 + PROWS) {
            float4 ov;
            ov.x = fmaf(wev, fmaxf(orawL.x + bdv, 0.f), bev);
            ov.y = fmaf(wev, fmaxf(orawL.y + bdv, 0.f), bev);
            ov.z = fmaf(wev, fmaxf(orawL.z + bdv, 0.f), bev);
            ov.w = fmaf(wev, fmaxf(orawL.w + bdv, 0.f), bev);
            *(float4*)(out + ib + (size_t)oL * W + col0) = ov;
        }
    }
}

// ---------------------------------------------------------------------------
extern "C" void kernel_launch(void* const* d_in, const int* in_sizes, int n_in,
                              void* d_out, int out_size)
{
    const float* x   = (const float*)d_in[0];
    const float* wa  = (const float*)d_in[1];
    const float* ba  = (const float*)d_in[2];
    const float* ga  = (const float*)d_in[3];
    const float* bta = (const float*)d_in[4];
    const float* ma  = (const float*)d_in[5];
    const float* va  = (const float*)d_in[6];
    const float* wb  = (const float*)d_in[7];
    const float* bb  = (const float*)d_in[8];
    const float* gb  = (const float*)d_in[9];
    const float* btb = (const float*)d_in[10];
    const float* mb  = (const float*)d_in[11];
    const float* vb  = (const float*)d_in[12];
    const float* wc  = (const float*)d_in[13];
    const float* bc  = (const float*)d_in[14];
    const float* gc  = (const float*)d_in[15];
    const float* btc = (const float*)d_in[16];
    const float* mc  = (const float*)d_in[17];
    const float* vc  = (const float*)d_in[18];
    const float* wd  = (const float*)d_in[19];
    const float* bd  = (const float*)d_in[20];
    const float* we  = (const float*)d_in[21];
    const float* be  = (const float*)d_in[22];
    float* out = (float*)d_out;

    dim3 g1(W / K1_COLS, SEGS, NB);
    k1_convA_colscan<<<g1, K1_COLS>>>(x, wa, ba, ga, bta, ma, va);

    k1b_carry<<<NB, 1024>>>();

    dim3 g23(H / PROWS, NB);
    k23_pencil<<<g23, 256>>>(
        x,
        wb, bb, gb, btb, mb, vb,
        wc, bc, gc, btc, mc, vc,
        wa, ba, ga, bta, ma, va,
        wd, bd, we, be,
        out);
}